// round 14
// baseline (speedup 1.0000x reference)
#include <cuda_runtime.h>
#include <math.h>

// Problem constants
#define SS 64
#define BB 32
#define DM 586
#define DE 583
#define NL 4
#define K1 17
#define CO1 16
#define CO2 8
#define P2LEN 38
#define CO3 32
#define T3 36
#define NV 128
#define MMW 31      // combined conv1+pool1+conv2+pool2 kernel length
#define XR 592      // smem x row stride (>= 586)

// Scratch (no allocations allowed)
__device__ float g_part[SS*2*2];              // per (s, half): {sum, sumsq}
__device__ float g_c2part[SS*8*CO2*P2LEN];    // raw superconv partials [s][g][c8][q]
__device__ unsigned g_scnt[SS];               // per-s arrival counters (monotonic)

// ---------------------------------------------------------------------------
// Single kernel. One block per (s, half), 1024 threads, grid = 128.
//  phase 0: stage w1 slice (this half's 16 ci, all co1) + w2 into smem.
//  phase 1: 32 warps gather 16 emb rows (2 warps/row, 10-deep MLP) + stats.
//  phase 2: build superconv weights W[cil][mm][c8] (S2 then window sums).
//  phase 3: superconv (stride-15, K=31) partials -> g_c2part; stats -> g_part.
//  phase 4 (last of 2 blocks per s, monotonic counter): BN affine fold,
//           o2 assembly, conv3, proj(128x36), argmax -> out. Tail reuses the
//           xs dynamic-smem region (dead after phase 3).
// ---------------------------------------------------------------------------
__global__ void __launch_bounds__(1024)
kF(const int* __restrict__ tokens, const float* __restrict__ emb,
   const float* __restrict__ pos,
   const float* __restrict__ gamma, const float* __restrict__ beta,
   const float* __restrict__ w1, const float* __restrict__ b1,
   const float* __restrict__ w2, const float* __restrict__ b2,
   const float* __restrict__ w3, const float* __restrict__ b3,
   const float* __restrict__ wl, const float* __restrict__ bl,
   float* __restrict__ out) {
    extern __shared__ float dyn[];
    float* xs  = dyn;                    // 16*XR   = 9472 floats
    float* sw1 = dyn + 16*XR;            // 4352: w1 slice [co1][cil*17+k]
    float* sS2 = sw1 + CO1*16*K1;        // 2176
    float* wsl = sS2 + 16*K1*CO2;        // 4096
    __shared__ float sw2s[CO2*CO1];      // 128
    __shared__ float sst[64];
    __shared__ float sws[CO1];
    __shared__ float sa8[CO2], sb8[CO2];
    __shared__ float sAC[2];
    __shared__ int   sh_last;

    int bx   = blockIdx.x;
    int s    = bx >> 1;
    int h    = bx & 1;
    int tid  = threadIdx.x;
    int wid  = tid >> 5;
    int lane = tid & 31;
    const float scale = sqrtf(586.0f);

    // ---------------- phase 0: stage weights ----------------
    for (int i = tid; i < CO1*16*K1; i += 1024) {
        int co1 = i / (16*K1);
        int off = i - co1*(16*K1);
        sw1[i] = w1[co1*(BB*K1) + h*(16*K1) + off];
    }
    if (tid < CO2*CO1) sw2s[tid] = w2[tid];

    // ---------------- phase 1: gather + stats ----------------
    {
        int ri   = wid >> 1;           // local row 0..15
        int part = wid & 1;
        int b    = h*16 + ri;
        int tok  = tokens[s*BB + b];
        const float* row = emb + (size_t)tok * DE;
        float sum = 0.f, sq = 0.f;
        int dbase = lane + 32*part;
        #pragma unroll
        for (int k = 0; k < 10; k++) {
            int d = dbase + 64*k;
            if (d < DE) {
                float v = row[d] * scale;
                xs[ri*XR + d] = v;
                sum += v; sq += v*v;
            }
        }
        if (part == 0 && lane < 3) {
            float v = pos[(s*BB + b)*3 + lane];
            xs[ri*XR + DE + lane] = v;
            sum += v; sq += v*v;
        }
        #pragma unroll
        for (int off = 16; off >= 1; off >>= 1) {
            sum += __shfl_down_sync(0xffffffffu, sum, off);
            sq  += __shfl_down_sync(0xffffffffu, sq,  off);
        }
        if (lane == 0) { sst[wid] = sum; sst[32 + wid] = sq; }
    }
    __syncthreads();
    if (wid == 0) {
        float a = sst[lane];
        float c = sst[32 + lane];
        #pragma unroll
        for (int off = 16; off >= 1; off >>= 1) {
            a += __shfl_down_sync(0xffffffffu, a, off);
            c += __shfl_down_sync(0xffffffffu, c, off);
        }
        if (lane == 0) {
            g_part[(s*2 + h)*2 + 0] = a;
            g_part[(s*2 + h)*2 + 1] = c;
        }
    }

    // ---------------- phase 2: weight build ----------------
    for (int e = tid; e < 16*K1*CO2; e += 1024) {
        int c8 = e & 7;
        int t  = e >> 3;
        int k  = t % K1;
        int ci = t / K1;
        float acc = 0.f;
        #pragma unroll
        for (int co1 = 0; co1 < CO1; co1++)
            acc += sw2s[c8*CO1 + co1] * sw1[co1*(16*K1) + ci*K1 + k];
        sS2[(ci*K1 + k)*CO2 + c8] = acc;
    }
    __syncthreads();
    for (int e = tid; e < 16*MMW*CO2; e += 1024) {
        int c8 = e & 7;
        int t  = e >> 3;
        int mm = t % MMW;
        int ci = t / MMW;
        int dlo = mm - (K1-1); if (dlo < 0) dlo = 0;
        int dhi = mm;          if (dhi > 14) dhi = 14;
        float acc = 0.f;
        for (int d = dlo; d <= dhi; d++)
            acc += sS2[(ci*K1 + (mm - d))*CO2 + c8];
        wsl[(ci*32 + mm)*CO2 + c8] = acc * (1.f/15.f);
    }
    __syncthreads();

    // ---------------- phase 3: superconv partials ----------------
    for (int t = tid; t < 4*CO2*P2LEN; t += 1024) {
        int q  = t % P2LEN;
        int rr = t / P2LEN;
        int c8 = rr & 7;
        int gg = rr >> 3;
        float acc0 = 0.f, acc1 = 0.f;
        const float* xb = xs + (gg*4)*XR + 15*q;
        #pragma unroll
        for (int ci = 0; ci < 4; ci++) {
            const float* xr = xb + ci*XR;
            const float* wp = wsl + (gg*4 + ci)*(32*CO2) + c8;
            #pragma unroll
            for (int mm = 0; mm < MMW; mm += 2) {
                acc0 += wp[mm*CO2] * xr[mm];
                if (mm + 1 < MMW) acc1 += wp[(mm+1)*CO2] * xr[mm+1];
            }
        }
        g_c2part[(s*8 + h*4 + gg)*(CO2*P2LEN) + c8*P2LEN + q] = acc0 + acc1;
    }

    // ---------------- arrival: last of 2 blocks per s runs the tail ---------
    __threadfence();
    __syncthreads();
    if (tid == 0) {
        unsigned old = atomicAdd(&g_scnt[s], 1u);
        sh_last = ((old & 1u) == 1u) ? 1 : 0;
        __threadfence();
    }
    __syncthreads();
    if (!sh_last) return;

    // ---------------- phase 4: tail (reuse xs region) ----------------
    float* twls = xs;                    // 4608
    float* tbls = xs + NV*T3;            // 128
    float* to2  = tbls + NV;             // 304
    float* to3  = to2 + CO2*P2LEN;       // 1152  (total 6192 < 9472)

    // wsum1[co1] from global w1 (L2-hot), warps 0..15
    if (wid < CO1) {
        float p = 0.f;
        for (int i = lane; i < BB*K1; i += 32) p += w1[wid*(BB*K1) + i];
        #pragma unroll
        for (int off = 16; off >= 1; off >>= 1)
            p += __shfl_down_sync(0xffffffffu, p, off);
        if (lane == 0) sws[wid] = p;
    }
    for (int i = tid; i < NV*T3; i += 1024) twls[i] = wl[i];
    if (tid < NV) tbls[tid] = bl[tid];
    __syncthreads();

    // BN affine (warp 0 lane 0) + ws2a/ws2b (warp 1)
    if (wid == 0 && lane == 0) {
        float invN = 1.f / (float)(BB*DM);
        float ts = __ldcg(&g_part[s*4 + 0]) + __ldcg(&g_part[s*4 + 2]);
        float tq = __ldcg(&g_part[s*4 + 1]) + __ldcg(&g_part[s*4 + 3]);
        float m = ts * invN;
        float v = tq * invN - m*m;   // biased var, matches reference
        float A = 1.f, Cf = 0.f;
        #pragma unroll
        for (int l = 0; l < NL; l++) {
            float gg = gamma[l*SS + s];
            float bb = beta[l*SS + s];
            float inv = rsqrtf(v + 1e-5f);
            float a = gg * inv;
            float c = bb - a * m;
            A = a * A;
            Cf = a * Cf + c;
            m = bb;
            v = a * a * v;
        }
        sAC[0] = A; sAC[1] = Cf;
    } else if (wid == 1 && lane < CO2) {
        float a = 0.f, bb = 0.f;
        #pragma unroll
        for (int co1 = 0; co1 < CO1; co1++) {
            float wv = sw2s[lane*CO1 + co1];
            a  += wv * sws[co1];
            bb += wv * b1[co1];
        }
        sa8[lane] = a;
        sb8[lane] = bb;
    }
    __syncthreads();

    float A = sAC[0], Cf = sAC[1];
    // o2 assembly: A*(sum of 8 partials) + Cf*ws2a + ws2b + b2
    {
        const float* pp = g_c2part + s*8*(CO2*P2LEN);
        for (int i = tid; i < CO2*P2LEN; i += 1024) {
            int c8 = i / P2LEN;
            float p0 = __ldcg(&pp[i]),         p1 = __ldcg(&pp[304 + i]);
            float p2 = __ldcg(&pp[2*304 + i]), p3 = __ldcg(&pp[3*304 + i]);
            float p4 = __ldcg(&pp[4*304 + i]), p5 = __ldcg(&pp[5*304 + i]);
            float p6 = __ldcg(&pp[6*304 + i]), p7 = __ldcg(&pp[7*304 + i]);
            float acc = ((p0 + p1) + (p2 + p3)) + ((p4 + p5) + (p6 + p7));
            to2[i] = A*acc + Cf*sa8[c8] + sb8[c8] + b2[c8];
        }
    }
    __syncthreads();

    // conv3: (8,38) -> (32,36), K=3
    for (int i = tid; i < CO3*T3; i += 1024) {
        int co = i / T3;
        int t  = i - co*T3;
        float acc = b3[co];
        #pragma unroll
        for (int c8 = 0; c8 < CO2; c8++) {
            const float* rr = to2 + c8*P2LEN + t;
            const float* w = w3 + (co*CO2 + c8)*3;
            acc += w[0]*rr[0] + w[1]*rr[1] + w[2]*rr[2];
        }
        to3[i] = acc;
    }
    __syncthreads();

    // projection to 128 vocab + argmax (first-max semantics like jnp.argmax)
    {
        int c  = tid >> 5;   // channel 0..31 (one warp per channel)
        int vl = lane;       // vocab lane 0..31
        float orow[T3];
        #pragma unroll
        for (int k = 0; k < T3; k++) orow[k] = to3[c*T3 + k];

        float bestv = -3.4e38f;
        int   besti = 0;
        #pragma unroll
        for (int i = 0; i < 4; i++) {
            int v = vl + 32*i;
            const float4* wr = (const float4*)(twls + v*T3);  // 9 float4
            float d0 = tbls[v], d1 = 0.f;
            #pragma unroll
            for (int k4 = 0; k4 < 9; k4 += 2) {
                float4 w4 = wr[k4];
                d0 += orow[4*k4+0]*w4.x + orow[4*k4+1]*w4.y
                    + orow[4*k4+2]*w4.z + orow[4*k4+3]*w4.w;
            }
            #pragma unroll
            for (int k4 = 1; k4 < 9; k4 += 2) {
                float4 w4 = wr[k4];
                d1 += orow[4*k4+0]*w4.x + orow[4*k4+1]*w4.y
                    + orow[4*k4+2]*w4.z + orow[4*k4+3]*w4.w;
            }
            float d = d0 + d1;
            if (d > bestv) { bestv = d; besti = v; }  // strict > keeps first max
        }
        #pragma unroll
        for (int off = 16; off >= 1; off >>= 1) {
            float ov = __shfl_down_sync(0xffffffffu, bestv, off);
            int   oi = __shfl_down_sync(0xffffffffu, besti, off);
            if (ov > bestv || (ov == bestv && oi < besti)) { bestv = ov; besti = oi; }
        }
        if (vl == 0) out[s*BB + c] = (float)besti;
    }
}

// ---------------------------------------------------------------------------
extern "C" void kernel_launch(void* const* d_in, const int* in_sizes, int n_in,
                              void* d_out, int out_size) {
    const int*   tokens = (const int*)  d_in[0];
    const float* emb    = (const float*)d_in[1];
    const float* pos    = (const float*)d_in[2];
    const float* gamma  = (const float*)d_in[3];
    const float* beta   = (const float*)d_in[4];
    const float* w1     = (const float*)d_in[5];
    const float* b1     = (const float*)d_in[6];
    const float* w2     = (const float*)d_in[7];
    const float* b2     = (const float*)d_in[8];
    const float* w3     = (const float*)d_in[9];
    const float* b3     = (const float*)d_in[10];
    const float* wl     = (const float*)d_in[11];
    const float* bl     = (const float*)d_in[12];
    float* out = (float*)d_out;

    size_t sh = (size_t)(16*XR + CO1*16*K1 + 16*K1*CO2 + 16*32*CO2) * sizeof(float); // 80384 B
    cudaFuncSetAttribute(kF, cudaFuncAttributeMaxDynamicSharedMemorySize, (int)sh);

    kF<<<2*SS, 1024, sh>>>(tokens, emb, pos, gamma, beta, w1, b1,
                           w2, b2, w3, b3, wl, bl, out);
}

// round 15
// speedup vs baseline: 1.1722x; 1.1722x over previous
#include <cuda_runtime.h>
#include <math.h>

// Problem constants
#define SS 64
#define BB 32
#define DM 586
#define DE 583
#define NL 4
#define K1 17
#define CO1 16
#define CO2 8
#define P2LEN 38
#define CO3 32
#define T3 36
#define NV 128
#define MMW 31      // combined conv1+pool1+conv2+pool2 kernel length
#define XR 592      // smem x row stride (>= 586)

// Scratch (no allocations allowed)
__device__ float g_part[SS*2*2];              // per (s, half): {sum, sumsq}
__device__ float g_c2part[SS*8*CO2*P2LEN];    // raw superconv partials [s][g][c8][q]
__device__ float g_hsum[2*CO1];               // per-half w1 row sums (identical writes)

// ---------------------------------------------------------------------------
// Kernel SC: one block per (s, half). 1024 threads, grid = 128.
//  phase 0: stage w1 slice (this half's 16 ci, all co1) + w2 into smem.
//  phase 1: 32 warps gather 16 emb rows (2 warps/row, 10-deep MLP) + stats;
//           warps 16-31 also compute per-half w1 sums -> g_hsum (benign
//           identical-value race across blocks of the same half).
//  phase 2: build superconv weights W[cil][mm][c8] (S2 then window sums).
//  phase 3: superconv (stride-15, K=31) partials -> g_c2part.
// ---------------------------------------------------------------------------
__global__ void __launch_bounds__(1024)
kSC(const int* __restrict__ tokens, const float* __restrict__ emb,
    const float* __restrict__ pos, const float* __restrict__ w1,
    const float* __restrict__ w2) {
    extern __shared__ float dyn[];
    float* xs  = dyn;                    // 16*XR   = 9472 floats
    float* sw1 = dyn + 16*XR;            // 4352: w1 slice [co1][cil*17+k]
    float* sS2 = sw1 + CO1*16*K1;        // 2176
    float* wsl = sS2 + 16*K1*CO2;        // 4096
    __shared__ float sw2s[CO2*CO1];      // 128
    __shared__ float sst[64];

    int bx   = blockIdx.x;
    int s    = bx >> 1;
    int h    = bx & 1;
    int tid  = threadIdx.x;
    int wid  = tid >> 5;
    int lane = tid & 31;
    const float scale = sqrtf(586.0f);

    // ---------------- phase 0: stage weights ----------------
    for (int i = tid; i < CO1*16*K1; i += 1024) {
        int co1 = i / (16*K1);
        int off = i - co1*(16*K1);
        sw1[i] = w1[co1*(BB*K1) + h*(16*K1) + off];
    }
    if (tid < CO2*CO1) sw2s[tid] = w2[tid];

    // ---------------- phase 1: gather + stats ----------------
    {
        int ri   = wid >> 1;           // local row 0..15
        int part = wid & 1;
        int b    = h*16 + ri;
        int tok  = tokens[s*BB + b];
        const float* row = emb + (size_t)tok * DE;
        float sum = 0.f, sq = 0.f;
        int dbase = lane + 32*part;
        #pragma unroll
        for (int k = 0; k < 10; k++) {
            int d = dbase + 64*k;
            if (d < DE) {
                float v = row[d] * scale;
                xs[ri*XR + d] = v;
                sum += v; sq += v*v;
            }
        }
        if (part == 0 && lane < 3) {
            float v = pos[(s*BB + b)*3 + lane];
            xs[ri*XR + DE + lane] = v;
            sum += v; sq += v*v;
        }
        #pragma unroll
        for (int off = 16; off >= 1; off >>= 1) {
            sum += __shfl_down_sync(0xffffffffu, sum, off);
            sq  += __shfl_down_sync(0xffffffffu, sq,  off);
        }
        if (lane == 0) { sst[wid] = sum; sst[32 + wid] = sq; }
    }
    __syncthreads();
    if (wid == 0) {
        float a = sst[lane];
        float c = sst[32 + lane];
        #pragma unroll
        for (int off = 16; off >= 1; off >>= 1) {
            a += __shfl_down_sync(0xffffffffu, a, off);
            c += __shfl_down_sync(0xffffffffu, c, off);
        }
        if (lane == 0) {
            g_part[(s*2 + h)*2 + 0] = a;
            g_part[(s*2 + h)*2 + 1] = c;
        }
    } else if (wid >= 16) {
        // per-half w1 row sums for this half's 16 ci (272 floats per co1)
        int co1 = wid - 16;
        float p = 0.f;
        for (int j = lane; j < 16*K1; j += 32) p += sw1[co1*(16*K1) + j];
        #pragma unroll
        for (int off = 16; off >= 1; off >>= 1)
            p += __shfl_down_sync(0xffffffffu, p, off);
        if (lane == 0) g_hsum[h*CO1 + co1] = p;   // identical across s: benign
    }

    // ---------------- phase 2: weight build ----------------
    for (int e = tid; e < 16*K1*CO2; e += 1024) {
        int c8 = e & 7;
        int t  = e >> 3;
        int k  = t % K1;
        int ci = t / K1;
        float acc = 0.f;
        #pragma unroll
        for (int co1 = 0; co1 < CO1; co1++)
            acc += sw2s[c8*CO1 + co1] * sw1[co1*(16*K1) + ci*K1 + k];
        sS2[(ci*K1 + k)*CO2 + c8] = acc;
    }
    __syncthreads();
    for (int e = tid; e < 16*MMW*CO2; e += 1024) {
        int c8 = e & 7;
        int t  = e >> 3;
        int mm = t % MMW;
        int ci = t / MMW;
        int dlo = mm - (K1-1); if (dlo < 0) dlo = 0;
        int dhi = mm;          if (dhi > 14) dhi = 14;
        float acc = 0.f;
        for (int d = dlo; d <= dhi; d++)
            acc += sS2[(ci*K1 + (mm - d))*CO2 + c8];
        wsl[(ci*32 + mm)*CO2 + c8] = acc * (1.f/15.f);
    }
    __syncthreads();

    // ---------------- phase 3: superconv partials ----------------
    for (int t = tid; t < 4*CO2*P2LEN; t += 1024) {
        int q  = t % P2LEN;
        int rr = t / P2LEN;
        int c8 = rr & 7;
        int gg = rr >> 3;
        float acc0 = 0.f, acc1 = 0.f;
        const float* xb = xs + (gg*4)*XR + 15*q;
        #pragma unroll
        for (int ci = 0; ci < 4; ci++) {
            const float* xr = xb + ci*XR;
            const float* wp = wsl + (gg*4 + ci)*(32*CO2) + c8;
            #pragma unroll
            for (int mm = 0; mm < MMW; mm += 2) {
                acc0 += wp[mm*CO2] * xr[mm];
                if (mm + 1 < MMW) acc1 += wp[(mm+1)*CO2] * xr[mm+1];
            }
        }
        g_c2part[(s*8 + h*4 + gg)*(CO2*P2LEN) + c8*P2LEN + q] = acc0 + acc1;
    }
}

// ---------------------------------------------------------------------------
// Kernel D: grid = 256 (64 s x 4 channel quarters), block = 256 (8 warps).
// Per block: BN affine fold, o2 assembly (redundant per quarter; cheap),
// conv3 for its 8 channels, then proj: warp-per-channel, lane-per-vocab
// (4 v each, wl read as float4 straight from global), shuffle argmax.
// ---------------------------------------------------------------------------
__global__ void __launch_bounds__(256)
kD(const float* __restrict__ gamma, const float* __restrict__ beta,
   const float* __restrict__ b1,
   const float* __restrict__ w2, const float* __restrict__ b2,
   const float* __restrict__ w3, const float* __restrict__ b3,
   const float* __restrict__ wl, const float* __restrict__ bl,
   float* __restrict__ out) {
    int s    = blockIdx.x >> 2;
    int cq   = blockIdx.x & 3;     // channels cq*8 .. cq*8+7
    int tid  = threadIdx.x;
    int wid  = tid >> 5;
    int lane = tid & 31;
    __shared__ float o2s[CO2*P2LEN];   // 304
    __shared__ float o3s[8*T3];        // 288
    __shared__ float sa8[CO2], sb8[CO2];

    // ws2a/ws2b from precomputed half-sums (threads 0..7)
    if (tid < CO2) {
        float a = 0.f, bb = 0.f;
        #pragma unroll
        for (int co1 = 0; co1 < CO1; co1++) {
            float wv = w2[tid*CO1 + co1];
            float ws = g_hsum[co1] + g_hsum[CO1 + co1];
            a  += wv * ws;
            bb += wv * b1[co1];
        }
        sa8[tid] = a;
        sb8[tid] = bb;
    }

    // BN affine fold (redundant per thread; broadcast loads)
    float A, Cf;
    {
        float invN = 1.f / (float)(BB*DM);
        float ts = g_part[s*4 + 0] + g_part[s*4 + 2];
        float tq = g_part[s*4 + 1] + g_part[s*4 + 3];
        float m = ts * invN;
        float v = tq * invN - m*m;   // biased var, matches reference
        A = 1.f; Cf = 0.f;
        #pragma unroll
        for (int l = 0; l < NL; l++) {
            float gg = gamma[l*SS + s];
            float bb = beta[l*SS + s];
            float inv = rsqrtf(v + 1e-5f);
            float a = gg * inv;
            float c = bb - a * m;
            A = a * A;
            Cf = a * Cf + c;
            m = bb;
            v = a * a * v;
        }
    }
    __syncthreads();

    // o2 assembly: A*(sum of 8 partials) + Cf*ws2a + ws2b + b2
    {
        const float* pp = g_c2part + s*8*(CO2*P2LEN);
        for (int i = tid; i < CO2*P2LEN; i += 256) {
            int c8 = i / P2LEN;
            float p0 = pp[i],         p1 = pp[304 + i];
            float p2 = pp[2*304 + i], p3 = pp[3*304 + i];
            float p4 = pp[4*304 + i], p5 = pp[5*304 + i];
            float p6 = pp[6*304 + i], p7 = pp[7*304 + i];
            float acc = ((p0 + p1) + (p2 + p3)) + ((p4 + p5) + (p6 + p7));
            o2s[i] = A*acc + Cf*sa8[c8] + sb8[c8] + b2[c8];
        }
    }
    __syncthreads();

    // conv3 for this quarter's 8 channels: (8,38) -> (8,36)
    for (int i = tid; i < 8*T3; i += 256) {
        int col = i / T3;
        int co  = cq*8 + col;
        int t   = i - col*T3;
        float acc = b3[co];
        #pragma unroll
        for (int c8 = 0; c8 < CO2; c8++) {
            const float* rr = o2s + c8*P2LEN + t;
            const float* w = w3 + (co*CO2 + c8)*3;
            acc += w[0]*rr[0] + w[1]*rr[1] + w[2]*rr[2];
        }
        o3s[i] = acc;
    }
    __syncthreads();

    // projection to 128 vocab + argmax (first-max semantics like jnp.argmax)
    // warp wid -> channel cq*8+wid; lane -> vocab v = lane + 32*i.
    {
        float orow[T3];
        #pragma unroll
        for (int k = 0; k < T3; k++) orow[k] = o3s[wid*T3 + k];

        float bestv = -3.4e38f;
        int   besti = 0;
        #pragma unroll
        for (int i = 0; i < 4; i++) {
            int v = lane + 32*i;
            const float4* wr = (const float4*)(wl + v*T3);  // 144B rows, 16B-aligned
            float d0 = bl[v], d1 = 0.f;
            #pragma unroll
            for (int k4 = 0; k4 < 9; k4 += 2) {
                float4 w4 = wr[k4];
                d0 += orow[4*k4+0]*w4.x + orow[4*k4+1]*w4.y
                    + orow[4*k4+2]*w4.z + orow[4*k4+3]*w4.w;
            }
            #pragma unroll
            for (int k4 = 1; k4 < 9; k4 += 2) {
                float4 w4 = wr[k4];
                d1 += orow[4*k4+0]*w4.x + orow[4*k4+1]*w4.y
                    + orow[4*k4+2]*w4.z + orow[4*k4+3]*w4.w;
            }
            float d = d0 + d1;
            if (d > bestv) { bestv = d; besti = v; }  // strict > keeps first max
        }
        #pragma unroll
        for (int off = 16; off >= 1; off >>= 1) {
            float ov = __shfl_down_sync(0xffffffffu, bestv, off);
            int   oi = __shfl_down_sync(0xffffffffu, besti, off);
            if (ov > bestv || (ov == bestv && oi < besti)) { bestv = ov; besti = oi; }
        }
        if (lane == 0) out[s*BB + cq*8 + wid] = (float)besti;
    }
}

// ---------------------------------------------------------------------------
extern "C" void kernel_launch(void* const* d_in, const int* in_sizes, int n_in,
                              void* d_out, int out_size) {
    const int*   tokens = (const int*)  d_in[0];
    const float* emb    = (const float*)d_in[1];
    const float* pos    = (const float*)d_in[2];
    const float* gamma  = (const float*)d_in[3];
    const float* beta   = (const float*)d_in[4];
    const float* w1     = (const float*)d_in[5];
    const float* b1     = (const float*)d_in[6];
    const float* w2     = (const float*)d_in[7];
    const float* b2     = (const float*)d_in[8];
    const float* w3     = (const float*)d_in[9];
    const float* b3     = (const float*)d_in[10];
    const float* wl     = (const float*)d_in[11];
    const float* bl     = (const float*)d_in[12];
    float* out = (float*)d_out;

    size_t sh = (size_t)(16*XR + CO1*16*K1 + 16*K1*CO2 + 16*32*CO2) * sizeof(float); // 80384 B
    cudaFuncSetAttribute(kSC, cudaFuncAttributeMaxDynamicSharedMemorySize, (int)sh);

    kSC<<<2*SS, 1024, sh>>>(tokens, emb, pos, w1, w2);
    kD<<<256, 256>>>(gamma, beta, b1, w2, b2, w3, b3, wl, bl, out);
}